// round 2
// baseline (speedup 1.0000x reference)
#include <cuda_runtime.h>
#include <cstdint>
#include <cstddef>

// Problem constants
#define MTOT 16384      // B*S = 4*4096
#define HDIM 2048       // H
#define CHID 512        // CH
#define KIN  6144       // 3*H

// Scratch (static device globals -- allocation-free rule)
__device__ float2 g_stats[3 * MTOT];                 // (mu, rstd) per (tensor,row)
__device__ float  g_hidden[(size_t)MTOT * CHID];     // GEMM1 output (post-GELU)

__device__ __forceinline__ float to_tf32(float x) {
    uint32_t o;
    asm("cvt.rna.tf32.f32 %0, %1;" : "=r"(o) : "f"(x));
    return __uint_as_float(o);
}

__device__ __forceinline__ float gelu_exact(float x) {
    return 0.5f * x * (1.0f + erff(x * 0.70710678118654752440f));
}

// ---------------------------------------------------------------------------
// Kernel 1: per-row LayerNorm statistics for the three input tensors.
// grid = (MTOT, 3), block = 256. Each block reduces one row of 2048 floats.
// ---------------------------------------------------------------------------
__global__ void __launch_bounds__(256) ln_stats_kernel(
    const float* __restrict__ xp,   // prev   (branch 0)
    const float* __restrict__ xu,   // u_t    (branch 1)
    const float* __restrict__ xz)   // z_t    (branch 2)
{
    const int m = blockIdx.x;
    const int t = blockIdx.y;
    const float* X = (t == 0) ? xp : ((t == 1) ? xu : xz);
    const float4* row = (const float4*)(X + (size_t)m * HDIM);

    float s = 0.f, sq = 0.f;
#pragma unroll
    for (int j = 0; j < 2; j++) {
        float4 v = row[threadIdx.x + j * 256];
        s  += v.x + v.y + v.z + v.w;
        sq += v.x * v.x + v.y * v.y + v.z * v.z + v.w * v.w;
    }

    __shared__ float s1[256], s2[256];
    s1[threadIdx.x] = s;
    s2[threadIdx.x] = sq;
    __syncthreads();
#pragma unroll
    for (int o = 128; o > 0; o >>= 1) {
        if (threadIdx.x < o) {
            s1[threadIdx.x] += s1[threadIdx.x + o];
            s2[threadIdx.x] += s2[threadIdx.x + o];
        }
        __syncthreads();
    }
    if (threadIdx.x == 0) {
        float mu  = s1[0] * (1.0f / HDIM);
        float var = s2[0] * (1.0f / HDIM) - mu * mu;
        g_stats[t * MTOT + m] = make_float2(mu, rsqrtf(var + 1e-5f));
    }
}

// ---------------------------------------------------------------------------
// Tiled tf32 mma.sync GEMM:  C[M,N] = A[M,K] @ W[N,K]^T  (+bias, opt GELU)
// BM=128, BN=64, BK=32, 256 threads = 8 warps (4 along M x 2 along N),
// warp tile 32x32 = 2x4 m16n8k8 mma tiles.
// LN_A: A is generated on-the-fly from the three raw inputs + LN stats.
// GELU: epilogue applies exact GELU and writes to g_hidden; else writes C.
// ---------------------------------------------------------------------------
template<bool LN_A, bool GELU, int N, int K>
__global__ void __launch_bounds__(256) gemm_tf32_kernel(
    const float* __restrict__ x0, const float* __restrict__ x1, const float* __restrict__ x2,
    const float* __restrict__ g0, const float* __restrict__ g1, const float* __restrict__ g2,
    const float* __restrict__ c0, const float* __restrict__ c1, const float* __restrict__ c2,
    const float* __restrict__ W,      // [N][K] row-major (k contiguous)
    const float* __restrict__ bias,   // [N]
    float* __restrict__ Cout)         // [M][N] (ignored when GELU -> g_hidden)
{
    constexpr int LDS_ = 36;          // BK + 4 pad; row stride 144B (16B-aligned)
    __shared__ __align__(16) float As[128 * LDS_];
    __shared__ __align__(16) float Bs[64 * LDS_];

    const int bm   = blockIdx.y * 128;
    const int bn   = blockIdx.x * 64;
    const int tid  = threadIdx.x;
    const int lane = tid & 31;
    const int warp = tid >> 5;
    const int warpM = warp & 3;       // 0..3 -> 32-row slices
    const int warpN = warp >> 2;      // 0..1 -> 32-col slices

    float acc[2][4][4];
#pragma unroll
    for (int i = 0; i < 2; i++)
#pragma unroll
        for (int j = 0; j < 4; j++)
#pragma unroll
            for (int r = 0; r < 4; r++) acc[i][j][r] = 0.f;

    for (int k0 = 0; k0 < K; k0 += 32) {
        // ---- stage A tile (128 x 32) : 4 float4 per thread ----
        if (LN_A) {
            const int t = k0 >> 11;                 // which tensor (2048-col blocks)
            const float* X = (t == 0) ? x0 : ((t == 1) ? x1 : x2);
            const float* G = (t == 0) ? g0 : ((t == 1) ? g1 : g2);
            const float* Bb = (t == 0) ? c0 : ((t == 1) ? c1 : c2);
            const int kb = k0 & 2047;
#pragma unroll
            for (int j = 0; j < 4; j++) {
                int i  = tid + j * 256;
                int r  = i >> 3;
                int kv = (i & 7) << 2;
                int m  = bm + r;
                float2 st = g_stats[t * MTOT + m];
                float4 v  = *(const float4*)(X + (size_t)m * HDIM + kb + kv);
                float4 gg = *(const float4*)(G + kb + kv);
                float4 bb = *(const float4*)(Bb + kb + kv);
                v.x = to_tf32((v.x - st.x) * st.y * gg.x + bb.x);
                v.y = to_tf32((v.y - st.x) * st.y * gg.y + bb.y);
                v.z = to_tf32((v.z - st.x) * st.y * gg.z + bb.z);
                v.w = to_tf32((v.w - st.x) * st.y * gg.w + bb.w);
                *(float4*)(&As[r * LDS_ + kv]) = v;
            }
        } else {
#pragma unroll
            for (int j = 0; j < 4; j++) {
                int i  = tid + j * 256;
                int r  = i >> 3;
                int kv = (i & 7) << 2;
                float4 v = *(const float4*)(g_hidden + (size_t)(bm + r) * K + k0 + kv);
                v.x = to_tf32(v.x); v.y = to_tf32(v.y);
                v.z = to_tf32(v.z); v.w = to_tf32(v.w);
                *(float4*)(&As[r * LDS_ + kv]) = v;
            }
        }
        // ---- stage B tile (64 x 32) : 2 float4 per thread ----
#pragma unroll
        for (int j = 0; j < 2; j++) {
            int i  = tid + j * 256;
            int r  = i >> 3;
            int kv = (i & 7) << 2;
            float4 v = *(const float4*)(W + (size_t)(bn + r) * K + k0 + kv);
            v.x = to_tf32(v.x); v.y = to_tf32(v.y);
            v.z = to_tf32(v.z); v.w = to_tf32(v.w);
            *(float4*)(&Bs[r * LDS_ + kv]) = v;
        }
        __syncthreads();

        // ---- mainloop over 4 k-steps of 8 ----
#pragma unroll
        for (int kk = 0; kk < 32; kk += 8) {
            uint32_t a[2][4], b[4][2];
            const int ac = kk + (lane & 3);
            const int ar = warpM * 32 + (lane >> 2);
#pragma unroll
            for (int mt = 0; mt < 2; mt++) {
                int r = ar + mt * 16;
                a[mt][0] = __float_as_uint(As[r * LDS_ + ac]);
                a[mt][1] = __float_as_uint(As[(r + 8) * LDS_ + ac]);
                a[mt][2] = __float_as_uint(As[r * LDS_ + ac + 4]);
                a[mt][3] = __float_as_uint(As[(r + 8) * LDS_ + ac + 4]);
            }
            const int br = warpN * 32 + (lane >> 2);
#pragma unroll
            for (int nt = 0; nt < 4; nt++) {
                int r = br + nt * 8;
                b[nt][0] = __float_as_uint(Bs[r * LDS_ + ac]);
                b[nt][1] = __float_as_uint(Bs[r * LDS_ + ac + 4]);
            }
#pragma unroll
            for (int mt = 0; mt < 2; mt++)
#pragma unroll
                for (int nt = 0; nt < 4; nt++)
                    asm volatile(
                        "mma.sync.aligned.m16n8k8.row.col.f32.tf32.tf32.f32 "
                        "{%0,%1,%2,%3}, {%4,%5,%6,%7}, {%8,%9}, {%0,%1,%2,%3};\n"
                        : "+f"(acc[mt][nt][0]), "+f"(acc[mt][nt][1]),
                          "+f"(acc[mt][nt][2]), "+f"(acc[mt][nt][3])
                        : "r"(a[mt][0]), "r"(a[mt][1]), "r"(a[mt][2]), "r"(a[mt][3]),
                          "r"(b[nt][0]), "r"(b[nt][1]));
        }
        __syncthreads();
    }

    // ---- epilogue ----
    float* Cdst = GELU ? g_hidden : Cout;
#pragma unroll
    for (int mt = 0; mt < 2; mt++) {
        int row = bm + warpM * 32 + mt * 16 + (lane >> 2);
#pragma unroll
        for (int nt = 0; nt < 4; nt++) {
            int col = bn + warpN * 32 + nt * 8 + ((lane & 3) << 1);
            float bs0 = bias[col], bs1 = bias[col + 1];
            float v0 = acc[mt][nt][0] + bs0;
            float v1 = acc[mt][nt][1] + bs1;
            float v2 = acc[mt][nt][2] + bs0;
            float v3 = acc[mt][nt][3] + bs1;
            if (GELU) {
                v0 = gelu_exact(v0); v1 = gelu_exact(v1);
                v2 = gelu_exact(v2); v3 = gelu_exact(v3);
            }
            Cdst[(size_t)row * N + col]           = v0;
            Cdst[(size_t)row * N + col + 1]       = v1;
            Cdst[(size_t)(row + 8) * N + col]     = v2;
            Cdst[(size_t)(row + 8) * N + col + 1] = v3;
        }
    }
}

// ---------------------------------------------------------------------------
extern "C" void kernel_launch(void* const* d_in, const int* in_sizes, int n_in,
                              void* d_out, int out_size)
{
    const float* u_t    = (const float*)d_in[0];
    const float* z_t    = (const float*)d_in[1];
    const float* prev   = (const float*)d_in[2];
    const float* prev_g = (const float*)d_in[3];
    const float* prev_b = (const float*)d_in[4];
    const float* u_g    = (const float*)d_in[5];
    const float* u_b    = (const float*)d_in[6];
    const float* z_g    = (const float*)d_in[7];
    const float* z_b    = (const float*)d_in[8];
    const float* W1     = (const float*)d_in[9];
    const float* b1     = (const float*)d_in[10];
    const float* W2     = (const float*)d_in[11];
    const float* b2     = (const float*)d_in[12];
    float* out = (float*)d_out;

    // 1) LN statistics for the three branches
    ln_stats_kernel<<<dim3(MTOT, 3), 256>>>(prev, u_t, z_t);

    // 2) GEMM1: hidden = gelu(LN-concat @ W1^T + b1)   [16384 x 512]
    //    concat order: [prev, u_t, z_t]
    gemm_tf32_kernel<true, true, CHID, KIN><<<dim3(CHID / 64, MTOT / 128), 256>>>(
        prev, u_t, z_t,
        prev_g, u_g, z_g,
        prev_b, u_b, z_b,
        W1, b1, nullptr);

    // 3) GEMM2: out = hidden @ W2^T + b2               [16384 x 2048]
    gemm_tf32_kernel<false, false, HDIM, CHID><<<dim3(HDIM / 64, MTOT / 128), 256>>>(
        nullptr, nullptr, nullptr,
        nullptr, nullptr, nullptr,
        nullptr, nullptr, nullptr,
        W2, b2, out);
}

// round 3
// speedup vs baseline: 1.0176x; 1.0176x over previous
#include <cuda_runtime.h>
#include <cstdint>
#include <cstddef>

// Problem constants
#define MTOT 16384      // B*S = 4*4096
#define HDIM 2048       // H
#define CHID 512        // CH
#define KIN  6144       // 3*H

// Scratch (static device globals -- allocation-free rule)
__device__ float2 g_stats[3 * MTOT];                 // (mu, rstd) per (tensor,row)
__device__ float  g_hidden[(size_t)MTOT * CHID];     // GEMM1 output (post-GELU)

__device__ __forceinline__ float to_tf32(float x) {
    uint32_t o;
    asm("cvt.rna.tf32.f32 %0, %1;" : "=r"(o) : "f"(x));
    return __uint_as_float(o);
}

__device__ __forceinline__ float gelu_exact(float x) {
    return 0.5f * x * (1.0f + erff(x * 0.70710678118654752440f));
}

// ---------------------------------------------------------------------------
// Kernel 1: per-row LayerNorm statistics for the three input tensors.
// grid = (MTOT, 3), block = 256. Each block reduces one row of 2048 floats.
// ---------------------------------------------------------------------------
__global__ void __launch_bounds__(256) ln_stats_kernel(
    const float* __restrict__ xp,   // prev   (branch 0)
    const float* __restrict__ xu,   // u_t    (branch 1)
    const float* __restrict__ xz)   // z_t    (branch 2)
{
    const int m = blockIdx.x;
    const int t = blockIdx.y;
    const float* X = (t == 0) ? xp : ((t == 1) ? xu : xz);
    const float4* row = (const float4*)(X + (size_t)m * HDIM);

    float s = 0.f, sq = 0.f;
#pragma unroll
    for (int j = 0; j < 2; j++) {
        float4 v = row[threadIdx.x + j * 256];
        s  += v.x + v.y + v.z + v.w;
        sq += v.x * v.x + v.y * v.y + v.z * v.z + v.w * v.w;
    }

    __shared__ float s1[256], s2[256];
    s1[threadIdx.x] = s;
    s2[threadIdx.x] = sq;
    __syncthreads();
#pragma unroll
    for (int o = 128; o > 0; o >>= 1) {
        if (threadIdx.x < o) {
            s1[threadIdx.x] += s1[threadIdx.x + o];
            s2[threadIdx.x] += s2[threadIdx.x + o];
        }
        __syncthreads();
    }
    if (threadIdx.x == 0) {
        float mu  = s1[0] * (1.0f / HDIM);
        float var = s2[0] * (1.0f / HDIM) - mu * mu;
        g_stats[t * MTOT + m] = make_float2(mu, rsqrtf(var + 1e-5f));
    }
}

// ---------------------------------------------------------------------------
// Tiled tf32 mma.sync GEMM:  C[M,N] = A[M,K] @ W[N,K]^T  (+bias, opt GELU)
// BM=128, BN=64, BK=32, 256 threads = 8 warps (4 along M x 2 along N),
// warp tile 32x32 = 2x4 m16n8k8 mma tiles.
// LN_A: A is generated on-the-fly from the three raw inputs + LN stats.
// GELU: epilogue applies exact GELU and writes to g_hidden; else writes C.
// ---------------------------------------------------------------------------
template<bool LN_A, bool GELU, int N, int K>
__global__ void __launch_bounds__(256) gemm_tf32_kernel(
    const float* __restrict__ x0, const float* __restrict__ x1, const float* __restrict__ x2,
    const float* __restrict__ g0, const float* __restrict__ g1, const float* __restrict__ g2,
    const float* __restrict__ c0, const float* __restrict__ c1, const float* __restrict__ c2,
    const float* __restrict__ W,      // [N][K] row-major (k contiguous)
    const float* __restrict__ bias,   // [N]
    float* __restrict__ Cout)         // [M][N] (ignored when GELU -> g_hidden)
{
    constexpr int LDS_ = 36;          // BK + 4 pad; row stride 144B (16B-aligned)
    __shared__ __align__(16) float As[128 * LDS_];
    __shared__ __align__(16) float Bs[64 * LDS_];

    const int bm   = blockIdx.y * 128;
    const int bn   = blockIdx.x * 64;
    const int tid  = threadIdx.x;
    const int lane = tid & 31;
    const int warp = tid >> 5;
    const int warpM = warp & 3;       // 0..3 -> 32-row slices
    const int warpN = warp >> 2;      // 0..1 -> 32-col slices

    float acc[2][4][4];
#pragma unroll
    for (int i = 0; i < 2; i++)
#pragma unroll
        for (int j = 0; j < 4; j++)
#pragma unroll
            for (int r = 0; r < 4; r++) acc[i][j][r] = 0.f;

    for (int k0 = 0; k0 < K; k0 += 32) {
        // ---- stage A tile (128 x 32) : 4 float4 per thread ----
        if (LN_A) {
            const int t = k0 >> 11;                 // which tensor (2048-col blocks)
            const float* X = (t == 0) ? x0 : ((t == 1) ? x1 : x2);
            const float* G = (t == 0) ? g0 : ((t == 1) ? g1 : g2);
            const float* Bb = (t == 0) ? c0 : ((t == 1) ? c1 : c2);
            const int kb = k0 & 2047;
#pragma unroll
            for (int j = 0; j < 4; j++) {
                int i  = tid + j * 256;
                int r  = i >> 3;
                int kv = (i & 7) << 2;
                int m  = bm + r;
                float2 st = g_stats[t * MTOT + m];
                float4 v  = *(const float4*)(X + (size_t)m * HDIM + kb + kv);
                float4 gg = *(const float4*)(G + kb + kv);
                float4 bb = *(const float4*)(Bb + kb + kv);
                v.x = to_tf32((v.x - st.x) * st.y * gg.x + bb.x);
                v.y = to_tf32((v.y - st.x) * st.y * gg.y + bb.y);
                v.z = to_tf32((v.z - st.x) * st.y * gg.z + bb.z);
                v.w = to_tf32((v.w - st.x) * st.y * gg.w + bb.w);
                *(float4*)(&As[r * LDS_ + kv]) = v;
            }
        } else {
#pragma unroll
            for (int j = 0; j < 4; j++) {
                int i  = tid + j * 256;
                int r  = i >> 3;
                int kv = (i & 7) << 2;
                float4 v = *(const float4*)(g_hidden + (size_t)(bm + r) * K + k0 + kv);
                v.x = to_tf32(v.x); v.y = to_tf32(v.y);
                v.z = to_tf32(v.z); v.w = to_tf32(v.w);
                *(float4*)(&As[r * LDS_ + kv]) = v;
            }
        }
        // ---- stage B tile (64 x 32) : 2 float4 per thread ----
#pragma unroll
        for (int j = 0; j < 2; j++) {
            int i  = tid + j * 256;
            int r  = i >> 3;
            int kv = (i & 7) << 2;
            float4 v = *(const float4*)(W + (size_t)(bn + r) * K + k0 + kv);
            v.x = to_tf32(v.x); v.y = to_tf32(v.y);
            v.z = to_tf32(v.z); v.w = to_tf32(v.w);
            *(float4*)(&Bs[r * LDS_ + kv]) = v;
        }
        __syncthreads();

        // ---- mainloop over 4 k-steps of 8 ----
#pragma unroll
        for (int kk = 0; kk < 32; kk += 8) {
            uint32_t a[2][4], b[4][2];
            const int ac = kk + (lane & 3);
            const int ar = warpM * 32 + (lane >> 2);
#pragma unroll
            for (int mt = 0; mt < 2; mt++) {
                int r = ar + mt * 16;
                a[mt][0] = __float_as_uint(As[r * LDS_ + ac]);
                a[mt][1] = __float_as_uint(As[(r + 8) * LDS_ + ac]);
                a[mt][2] = __float_as_uint(As[r * LDS_ + ac + 4]);
                a[mt][3] = __float_as_uint(As[(r + 8) * LDS_ + ac + 4]);
            }
            const int br = warpN * 32 + (lane >> 2);
#pragma unroll
            for (int nt = 0; nt < 4; nt++) {
                int r = br + nt * 8;
                b[nt][0] = __float_as_uint(Bs[r * LDS_ + ac]);
                b[nt][1] = __float_as_uint(Bs[r * LDS_ + ac + 4]);
            }
#pragma unroll
            for (int mt = 0; mt < 2; mt++)
#pragma unroll
                for (int nt = 0; nt < 4; nt++)
                    asm volatile(
                        "mma.sync.aligned.m16n8k8.row.col.f32.tf32.tf32.f32 "
                        "{%0,%1,%2,%3}, {%4,%5,%6,%7}, {%8,%9}, {%0,%1,%2,%3};\n"
                        : "+f"(acc[mt][nt][0]), "+f"(acc[mt][nt][1]),
                          "+f"(acc[mt][nt][2]), "+f"(acc[mt][nt][3])
                        : "r"(a[mt][0]), "r"(a[mt][1]), "r"(a[mt][2]), "r"(a[mt][3]),
                          "r"(b[nt][0]), "r"(b[nt][1]));
        }
        __syncthreads();
    }

    // ---- epilogue ----
    float* Cdst = GELU ? g_hidden : Cout;
#pragma unroll
    for (int mt = 0; mt < 2; mt++) {
        int row = bm + warpM * 32 + mt * 16 + (lane >> 2);
#pragma unroll
        for (int nt = 0; nt < 4; nt++) {
            int col = bn + warpN * 32 + nt * 8 + ((lane & 3) << 1);
            float bs0 = bias[col], bs1 = bias[col + 1];
            float v0 = acc[mt][nt][0] + bs0;
            float v1 = acc[mt][nt][1] + bs1;
            float v2 = acc[mt][nt][2] + bs0;
            float v3 = acc[mt][nt][3] + bs1;
            if (GELU) {
                v0 = gelu_exact(v0); v1 = gelu_exact(v1);
                v2 = gelu_exact(v2); v3 = gelu_exact(v3);
            }
            Cdst[(size_t)row * N + col]           = v0;
            Cdst[(size_t)row * N + col + 1]       = v1;
            Cdst[(size_t)(row + 8) * N + col]     = v2;
            Cdst[(size_t)(row + 8) * N + col + 1] = v3;
        }
    }
}

// ---------------------------------------------------------------------------
extern "C" void kernel_launch(void* const* d_in, const int* in_sizes, int n_in,
                              void* d_out, int out_size)
{
    const float* u_t    = (const float*)d_in[0];
    const float* z_t    = (const float*)d_in[1];
    const float* prev   = (const float*)d_in[2];
    const float* prev_g = (const float*)d_in[3];
    const float* prev_b = (const float*)d_in[4];
    const float* u_g    = (const float*)d_in[5];
    const float* u_b    = (const float*)d_in[6];
    const float* z_g    = (const float*)d_in[7];
    const float* z_b    = (const float*)d_in[8];
    const float* W1     = (const float*)d_in[9];
    const float* b1     = (const float*)d_in[10];
    const float* W2     = (const float*)d_in[11];
    const float* b2     = (const float*)d_in[12];
    float* out = (float*)d_out;

    // 1) LN statistics for the three branches
    ln_stats_kernel<<<dim3(MTOT, 3), 256>>>(prev, u_t, z_t);

    // 2) GEMM1: hidden = gelu(LN-concat @ W1^T + b1)   [16384 x 512]
    //    concat order: [prev, u_t, z_t]
    gemm_tf32_kernel<true, true, CHID, KIN><<<dim3(CHID / 64, MTOT / 128), 256>>>(
        prev, u_t, z_t,
        prev_g, u_g, z_g,
        prev_b, u_b, z_b,
        W1, b1, nullptr);

    // 3) GEMM2: out = hidden @ W2^T + b2               [16384 x 2048]
    gemm_tf32_kernel<false, false, HDIM, CHID><<<dim3(HDIM / 64, MTOT / 128), 256>>>(
        nullptr, nullptr, nullptr,
        nullptr, nullptr, nullptr,
        nullptr, nullptr, nullptr,
        W2, b2, out);
}